// round 8
// baseline (speedup 1.0000x reference)
#include <cuda_runtime.h>
#include <math.h>

#define GAMMA 0.99f
#define LAM   0.95f
#define GL    (GAMMA * LAM)
#define EPSN  1e-8

#define CHUNKS 64
#define MAXN   8192
#define TPB    256
#define MAXB   512          // grid size for T=2048, N=8192

// Static device scratch (no allocations allowed). All zero-initialized.
__device__ float2   g_CD[CHUNKS * MAXN];   // {C, D} per (chunk, col)  4 MB
__device__ float    g_carry[CHUNKS * MAXN];
__device__ double   g_part[2 * MAXB];
__device__ unsigned g_c0, g_c1, g_cpre;    // barrier counters (self-resetting)
__device__ unsigned g_rel;                 // monotonic release epoch (never reset)
__device__ float    g_mean;
__device__ float    g_inv;                 // 1 / (std + eps)

__device__ __forceinline__ unsigned vld(const unsigned* p) {
    return *(const volatile unsigned*)p;
}

// ---------------------------------------------------------------------------
// Single persistent kernel. Grid = CHUNKS*(N/4)/TPB blocks, single wave
// (launch_bounds(256,4) -> <=64 regs, 4KB smem -> 4 blocks/SM, 592 >= 512).
//
// Part A: per (chunk, 4-col) thread, compose reverse recurrence into
//         a_out = D + C*a_in; keep sufficient stats IN REGISTERS.
// bar0  : grid barrier.
// Scan  : first N threads reverse-scan {C,D} over chunks -> carries.
// bar1  : grid barrier (block 0 resets c0 after).
// Stats : each thread evaluates its chunk's sum/sumsq contribution from its
//         register stats + its carries; block-reduce (double) -> partials;
//         LAST block to arrive reduces all partials -> mean, 1/(std+eps),
//         resets c1/cpre, bumps epoch g_rel.
// bar2  : wait on epoch.
// Part C: replay recurrence with carry; write normalized adv + returns.
// ---------------------------------------------------------------------------
__global__ __launch_bounds__(TPB, 4)
void gae_fused(const float* __restrict__ rw, const float* __restrict__ val,
               const int* __restrict__ dn, float* __restrict__ adv,
               float* __restrict__ ret, int N, int L, long long M) {
    const int groups = N >> 2;
    const int total  = CHUNKS * groups;
    const unsigned nb = gridDim.x;
    const int tid = blockIdx.x * TPB + threadIdx.x;

    int c = 0, g = 0, col = 0, t0 = 0, t1 = 0;
    const bool active = (tid < total);
    if (active) {
        c = tid / groups;  g = tid - c * groups;  col = g << 2;
        t0 = c * L;  t1 = t0 + L - 1;
    }

    float C[4]  = {1.f, 1.f, 1.f, 1.f};
    float D[4]  = {0.f, 0.f, 0.f, 0.f};
    float S1[4] = {0.f, 0.f, 0.f, 0.f};
    float SC[4] = {0.f, 0.f, 0.f, 0.f};
    float S2[4] = {0.f, 0.f, 0.f, 0.f};
    float SDC[4]= {0.f, 0.f, 0.f, 0.f};
    float SC2[4]= {0.f, 0.f, 0.f, 0.f};

    // ---- Part A ----
    if (active) {
        float4 vn = *reinterpret_cast<const float4*>(val + (size_t)(t1 + 1) * N + col);
        #pragma unroll 4
        for (int t = t1; t >= t0; --t) {
            float4 r  = *reinterpret_cast<const float4*>(rw + (size_t)t * N + col);
            int4   dd = *reinterpret_cast<const int4*>(dn + (size_t)t * N + col);
            float4 vc = *reinterpret_cast<const float4*>(val + (size_t)t * N + col);

            float rr[4] = {r.x, r.y, r.z, r.w};
            float vv[4] = {vc.x, vc.y, vc.z, vc.w};
            float vnn[4]= {vn.x, vn.y, vn.z, vn.w};
            int   di[4] = {dd.x, dd.y, dd.z, dd.w};

            #pragma unroll
            for (int j = 0; j < 4; ++j) {
                float nt  = di[j] ? 0.f : 1.f;
                float del = fmaf(GAMMA * nt, vnn[j], rr[j]) - vv[j];
                float cf  = GL * nt;
                D[j] = fmaf(cf, D[j], del);
                C[j] *= cf;
                S1[j] += D[j];
                SC[j] += C[j];
                S2[j]  = fmaf(D[j], D[j], S2[j]);
                SDC[j] = fmaf(D[j], C[j], SDC[j]);
                SC2[j] = fmaf(C[j], C[j], SC2[j]);
            }
            vn = vc;
        }
        size_t o = (size_t)c * N + col;
        #pragma unroll
        for (int j = 0; j < 4; ++j)
            g_CD[o + j] = make_float2(C[j], D[j]);
    }

    // ---- barrier 0 ----
    __threadfence();
    if (threadIdx.x == 0) {
        atomicAdd(&g_c0, 1u);
        while (vld(&g_c0) < nb) __nanosleep(64);
        __threadfence();
    }
    __syncthreads();

    // ---- Scan (first N threads) ----
    if (tid < N) {
        float a = 0.f;
        #pragma unroll 8
        for (int cc = CHUNKS - 1; cc >= 0; --cc) {
            size_t o = (size_t)cc * N + tid;
            g_carry[o] = a;
            float2 cd = g_CD[o];
            a = fmaf(cd.x, a, cd.y);
        }
    }

    // ---- barrier 1 ----
    __threadfence();
    if (threadIdx.x == 0) {
        atomicAdd(&g_c1, 1u);
        while (vld(&g_c1) < nb) __nanosleep(64);
        if (blockIdx.x == 0) g_c0 = 0u;   // safe: all blocks passed bar0
        __threadfence();
    }
    __syncthreads();

    // ---- Stats from registers + carries ----
    float ts = 0.f, ts2 = 0.f;
    float a4[4] = {0.f, 0.f, 0.f, 0.f};
    if (active) {
        size_t o = (size_t)c * N + col;
        #pragma unroll
        for (int j = 0; j < 4; ++j) {
            float a = g_carry[o + j];
            a4[j] = a;
            ts  += fmaf(SC[j], a, S1[j]);
            ts2 += fmaf(fmaf(SC2[j], a, 2.f * SDC[j]), a, S2[j]);
        }
    }
    __shared__ double ss[TPB];
    __shared__ double ss2[TPB];
    ss[threadIdx.x]  = (double)ts;
    ss2[threadIdx.x] = (double)ts2;
    __syncthreads();
    for (int st = TPB / 2; st > 0; st >>= 1) {
        if (threadIdx.x < st) {
            ss[threadIdx.x]  += ss[threadIdx.x + st];
            ss2[threadIdx.x] += ss2[threadIdx.x + st];
        }
        __syncthreads();
    }

    __shared__ unsigned s_snap;
    __shared__ bool     s_last;
    if (threadIdx.x == 0) {
        g_part[2 * blockIdx.x]     = ss[0];
        g_part[2 * blockIdx.x + 1] = ss2[0];
        s_snap = vld(&g_rel);              // snapshot BEFORE our arrival
        __threadfence();
        unsigned old = atomicAdd(&g_cpre, 1u);
        s_last = (old == nb - 1u);
    }
    __syncthreads();

    if (s_last) {                           // last block: fixed-order final reduce
        double s = 0.0, s2 = 0.0;
        for (int i = threadIdx.x; i < (int)nb; i += TPB) {
            s  += g_part[2 * i];
            s2 += g_part[2 * i + 1];
        }
        ss[threadIdx.x]  = s;
        ss2[threadIdx.x] = s2;
        __syncthreads();
        for (int st = TPB / 2; st > 0; st >>= 1) {
            if (threadIdx.x < st) {
                ss[threadIdx.x]  += ss[threadIdx.x + st];
                ss2[threadIdx.x] += ss2[threadIdx.x + st];
            }
            __syncthreads();
        }
        if (threadIdx.x == 0) {
            double mean = ss[0] / (double)M;
            double var  = (ss2[0] - ss[0] * ss[0] / (double)M) / (double)(M - 1);
            if (var < 0.0) var = 0.0;
            g_mean = (float)mean;
            g_inv  = (float)(1.0 / (sqrt(var) + EPSN));
            g_c1   = 0u;                    // safe: all passed bar1
            g_cpre = 0u;                    // safe: all arrived here
            __threadfence();
            atomicAdd(&g_rel, 1u);          // release epoch
        }
    }
    if (threadIdx.x == 0) {
        while (vld(&g_rel) == s_snap) __nanosleep(64);
        __threadfence();
    }
    __syncthreads();

    // ---- Part C: write pass ----
    if (active) {
        float m   = g_mean;
        float inv = g_inv;
        float4 a  = make_float4(a4[0], a4[1], a4[2], a4[3]);
        float4 vn = *reinterpret_cast<const float4*>(val + (size_t)(t1 + 1) * N + col);

        #pragma unroll 4
        for (int t = t1; t >= t0; --t) {
            float4 r  = *reinterpret_cast<const float4*>(rw + (size_t)t * N + col);
            int4   dd = *reinterpret_cast<const int4*>(dn + (size_t)t * N + col);
            float4 vc = *reinterpret_cast<const float4*>(val + (size_t)t * N + col);

            float nt, del;
            nt = dd.x ? 0.f : 1.f; del = fmaf(GAMMA * nt, vn.x, r.x) - vc.x;
            a.x = fmaf(GL * nt, a.x, del);
            nt = dd.y ? 0.f : 1.f; del = fmaf(GAMMA * nt, vn.y, r.y) - vc.y;
            a.y = fmaf(GL * nt, a.y, del);
            nt = dd.z ? 0.f : 1.f; del = fmaf(GAMMA * nt, vn.z, r.z) - vc.z;
            a.z = fmaf(GL * nt, a.z, del);
            nt = dd.w ? 0.f : 1.f; del = fmaf(GAMMA * nt, vn.w, r.w) - vc.w;
            a.w = fmaf(GL * nt, a.w, del);

            size_t o = (size_t)t * N + col;
            *reinterpret_cast<float4*>(adv + o) =
                make_float4((a.x - m) * inv, (a.y - m) * inv,
                            (a.z - m) * inv, (a.w - m) * inv);
            *reinterpret_cast<float4*>(ret + o) =
                make_float4(a.x + vc.x, a.y + vc.y, a.z + vc.z, a.w + vc.w);

            vn = vc;
        }
    }
}

extern "C" void kernel_launch(void* const* d_in, const int* in_sizes, int n_in,
                              void* d_out, int out_size) {
    const float* rw  = (const float*)d_in[0];   // rewards [T, N]
    const float* val = (const float*)d_in[1];   // values  [T+1, N]
    const int*   dn  = (const int*)d_in[2];     // dones   [T, N]
    float* out = (float*)d_out;                 // [adv_norm TN | returns TN]

    int TN = in_sizes[0];
    int N  = in_sizes[1] - in_sizes[0];
    int T  = TN / N;
    int L  = T / CHUNKS;

    int groups = N >> 2;
    int blocks = (CHUNKS * groups + TPB - 1) / TPB;   // 512 for T=2048,N=8192

    float* adv = out;
    float* ret = out + (size_t)TN;

    gae_fused<<<blocks, TPB>>>(rw, val, dn, adv, ret, N, L, (long long)TN);
}

// round 9
// speedup vs baseline: 1.1454x; 1.1454x over previous
#include <cuda_runtime.h>
#include <math.h>

#define GAMMA 0.99f
#define LAM   0.95f
#define GL    (GAMMA * LAM)
#define EPSN  1e-8

#define CHUNKS 64
#define MAXN   8192
#define TPB    256
#define MAXB   512          // grid size for T=2048, N=8192 (single wave: 4/SM*148=592>=512)

// Static device scratch (no allocations allowed). All zero-initialized.
__device__ float2   g_CD[CHUNKS * MAXN];   // {C, D} per (chunk, col)  4 MB
__device__ float    g_carry[CHUNKS * MAXN];
__device__ double   g_part[2 * MAXB];
__device__ unsigned g_c0, g_c1, g_cpre;    // barrier counters (self-resetting)
__device__ unsigned g_rel;                 // monotonic release epoch (never reset)
__device__ float    g_mean;
__device__ float    g_inv;                 // 1 / (std + eps)

__device__ __forceinline__ unsigned vld(const unsigned* p) {
    return *(const volatile unsigned*)p;
}

// ---------------------------------------------------------------------------
// Single persistent kernel, single wave.
// Part A : per (chunk, 4-col) thread, compose reverse recurrence into
//          a_out = D + C*a_in; stats accumulated in registers, then STASHED
//          TO SMEM so they don't inflate register liveness across barriers.
// bar0   : grid barrier (CD ready).
// Scan   : DISTRIBUTED — 16 workers per block (lanes 0..15), one column each,
//          reverse-scan {C,D} over chunks -> carries. g_CD is L2-resident.
// bar1   : grid barrier (carries ready; block 0 resets c0).
// Stats  : reload stats from smem, read own carries, closed-form sum/sumsq,
//          block reduce (double), last-arriving block reduces partials in
//          fixed order -> mean, 1/(std+eps); resets counters; bumps epoch.
// bar2   : wait on epoch.
// Part C : replay recurrence with carry; write normalized adv + returns.
// ---------------------------------------------------------------------------
__global__ __launch_bounds__(TPB, 4)
void gae_fused(const float* __restrict__ rw, const float* __restrict__ val,
               const int* __restrict__ dn, float* __restrict__ adv,
               float* __restrict__ ret, int N, int L, long long M) {
    const int groups = N >> 2;
    const int total  = CHUNKS * groups;
    const unsigned nb = gridDim.x;
    const int tid = blockIdx.x * TPB + threadIdx.x;

    __shared__ float  s_st[20][TPB];   // stat stash: S1,SC,S2,SDC,SC2 x4
    __shared__ double ss[TPB];
    __shared__ double ss2[TPB];

    int c = 0, g = 0, col = 0, t0 = 0, t1 = 0;
    const bool active = (tid < total);
    if (active) {
        c = tid / groups;  g = tid - c * groups;  col = g << 2;
        t0 = c * L;  t1 = t0 + L - 1;
    }

    // ---- Part A ----
    if (active) {
        float C[4]  = {1.f, 1.f, 1.f, 1.f};
        float D[4]  = {0.f, 0.f, 0.f, 0.f};
        float S1[4] = {0.f, 0.f, 0.f, 0.f};
        float SC[4] = {0.f, 0.f, 0.f, 0.f};
        float S2[4] = {0.f, 0.f, 0.f, 0.f};
        float SDC[4]= {0.f, 0.f, 0.f, 0.f};
        float SC2[4]= {0.f, 0.f, 0.f, 0.f};

        float4 vn = *reinterpret_cast<const float4*>(val + (size_t)(t1 + 1) * N + col);
        #pragma unroll 4
        for (int t = t1; t >= t0; --t) {
            float4 r  = *reinterpret_cast<const float4*>(rw + (size_t)t * N + col);
            int4   dd = *reinterpret_cast<const int4*>(dn + (size_t)t * N + col);
            float4 vc = *reinterpret_cast<const float4*>(val + (size_t)t * N + col);

            float rr[4] = {r.x, r.y, r.z, r.w};
            float vv[4] = {vc.x, vc.y, vc.z, vc.w};
            float vnn[4]= {vn.x, vn.y, vn.z, vn.w};
            int   di[4] = {dd.x, dd.y, dd.z, dd.w};

            #pragma unroll
            for (int j = 0; j < 4; ++j) {
                float nt  = di[j] ? 0.f : 1.f;
                float del = fmaf(GAMMA * nt, vnn[j], rr[j]) - vv[j];
                float cf  = GL * nt;
                D[j] = fmaf(cf, D[j], del);
                C[j] *= cf;
                S1[j] += D[j];
                SC[j] += C[j];
                S2[j]  = fmaf(D[j], D[j], S2[j]);
                SDC[j] = fmaf(D[j], C[j], SDC[j]);
                SC2[j] = fmaf(C[j], C[j], SC2[j]);
            }
            vn = vc;
        }
        size_t o = (size_t)c * N + col;
        #pragma unroll
        for (int j = 0; j < 4; ++j) {
            g_CD[o + j] = make_float2(C[j], D[j]);
            s_st[j     ][threadIdx.x] = S1[j];
            s_st[j + 4 ][threadIdx.x] = SC[j];
            s_st[j + 8 ][threadIdx.x] = S2[j];
            s_st[j + 12][threadIdx.x] = SDC[j];
            s_st[j + 16][threadIdx.x] = SC2[j];
        }
    }

    // ---- barrier 0 (CD ready) ----
    __threadfence();
    __syncthreads();
    if (threadIdx.x == 0) {
        atomicAdd(&g_c0, 1u);
        while (vld(&g_c0) < nb) __nanosleep(64);
        __threadfence();
    }
    __syncthreads();

    // ---- Distributed scan: 16 workers/block, one column each ----
    {
        int colw = blockIdx.x * 16 + threadIdx.x;   // lanes 0..15 only
        if (threadIdx.x < 16 && colw < N) {
            float a = 0.f;
            #pragma unroll 8
            for (int cc = CHUNKS - 1; cc >= 0; --cc) {
                size_t o = (size_t)cc * N + colw;
                g_carry[o] = a;
                float2 cd = g_CD[o];
                a = fmaf(cd.x, a, cd.y);
            }
        }
    }

    // ---- barrier 1 (carries ready) ----
    __threadfence();
    if (threadIdx.x == 0) {
        atomicAdd(&g_c1, 1u);
        while (vld(&g_c1) < nb) __nanosleep(64);
        if (blockIdx.x == 0) g_c0 = 0u;   // safe: all blocks passed bar0
        __threadfence();
    }
    __syncthreads();

    // ---- Stats: reload from smem stash + own carries ----
    float ts = 0.f, ts2 = 0.f;
    float a4[4] = {0.f, 0.f, 0.f, 0.f};
    if (active) {
        size_t o = (size_t)c * N + col;
        #pragma unroll
        for (int j = 0; j < 4; ++j) {
            float a   = g_carry[o + j];
            float S1  = s_st[j     ][threadIdx.x];
            float SC  = s_st[j + 4 ][threadIdx.x];
            float S2  = s_st[j + 8 ][threadIdx.x];
            float SDC = s_st[j + 12][threadIdx.x];
            float SC2 = s_st[j + 16][threadIdx.x];
            a4[j] = a;
            ts  += fmaf(SC, a, S1);
            ts2 += fmaf(fmaf(SC2, a, 2.f * SDC), a, S2);
        }
    }
    ss[threadIdx.x]  = (double)ts;
    ss2[threadIdx.x] = (double)ts2;
    __syncthreads();
    for (int st = TPB / 2; st > 0; st >>= 1) {
        if (threadIdx.x < st) {
            ss[threadIdx.x]  += ss[threadIdx.x + st];
            ss2[threadIdx.x] += ss2[threadIdx.x + st];
        }
        __syncthreads();
    }

    __shared__ unsigned s_snap;
    __shared__ bool     s_last;
    if (threadIdx.x == 0) {
        g_part[2 * blockIdx.x]     = ss[0];
        g_part[2 * blockIdx.x + 1] = ss2[0];
        s_snap = vld(&g_rel);              // snapshot BEFORE our arrival
        __threadfence();
        unsigned old = atomicAdd(&g_cpre, 1u);
        s_last = (old == nb - 1u);
    }
    __syncthreads();

    if (s_last) {                           // last block: fixed-order final reduce
        double s = 0.0, s2 = 0.0;
        for (int i = threadIdx.x; i < (int)nb; i += TPB) {
            s  += g_part[2 * i];
            s2 += g_part[2 * i + 1];
        }
        ss[threadIdx.x]  = s;
        ss2[threadIdx.x] = s2;
        __syncthreads();
        for (int st = TPB / 2; st > 0; st >>= 1) {
            if (threadIdx.x < st) {
                ss[threadIdx.x]  += ss[threadIdx.x + st];
                ss2[threadIdx.x] += ss2[threadIdx.x + st];
            }
            __syncthreads();
        }
        if (threadIdx.x == 0) {
            double mean = ss[0] / (double)M;
            double var  = (ss2[0] - ss[0] * ss[0] / (double)M) / (double)(M - 1);
            if (var < 0.0) var = 0.0;
            g_mean = (float)mean;
            g_inv  = (float)(1.0 / (sqrt(var) + EPSN));
            g_c1   = 0u;                    // safe: all passed bar1
            g_cpre = 0u;                    // safe: all arrived here
            __threadfence();
            atomicAdd(&g_rel, 1u);          // release epoch
        }
    }
    if (threadIdx.x == 0) {
        while (vld(&g_rel) == s_snap) __nanosleep(64);
        __threadfence();
    }
    __syncthreads();

    // ---- Part C: write pass ----
    if (active) {
        float m   = g_mean;
        float inv = g_inv;
        float4 a  = make_float4(a4[0], a4[1], a4[2], a4[3]);
        float4 vn = *reinterpret_cast<const float4*>(val + (size_t)(t1 + 1) * N + col);

        #pragma unroll 4
        for (int t = t1; t >= t0; --t) {
            float4 r  = *reinterpret_cast<const float4*>(rw + (size_t)t * N + col);
            int4   dd = *reinterpret_cast<const int4*>(dn + (size_t)t * N + col);
            float4 vc = *reinterpret_cast<const float4*>(val + (size_t)t * N + col);

            float nt, del;
            nt = dd.x ? 0.f : 1.f; del = fmaf(GAMMA * nt, vn.x, r.x) - vc.x;
            a.x = fmaf(GL * nt, a.x, del);
            nt = dd.y ? 0.f : 1.f; del = fmaf(GAMMA * nt, vn.y, r.y) - vc.y;
            a.y = fmaf(GL * nt, a.y, del);
            nt = dd.z ? 0.f : 1.f; del = fmaf(GAMMA * nt, vn.z, r.z) - vc.z;
            a.z = fmaf(GL * nt, a.z, del);
            nt = dd.w ? 0.f : 1.f; del = fmaf(GAMMA * nt, vn.w, r.w) - vc.w;
            a.w = fmaf(GL * nt, a.w, del);

            size_t o = (size_t)t * N + col;
            *reinterpret_cast<float4*>(adv + o) =
                make_float4((a.x - m) * inv, (a.y - m) * inv,
                            (a.z - m) * inv, (a.w - m) * inv);
            *reinterpret_cast<float4*>(ret + o) =
                make_float4(a.x + vc.x, a.y + vc.y, a.z + vc.z, a.w + vc.w);

            vn = vc;
        }
    }
}

extern "C" void kernel_launch(void* const* d_in, const int* in_sizes, int n_in,
                              void* d_out, int out_size) {
    const float* rw  = (const float*)d_in[0];   // rewards [T, N]
    const float* val = (const float*)d_in[1];   // values  [T+1, N]
    const int*   dn  = (const int*)d_in[2];     // dones   [T, N]
    float* out = (float*)d_out;                 // [adv_norm TN | returns TN]

    int TN = in_sizes[0];
    int N  = in_sizes[1] - in_sizes[0];
    int T  = TN / N;
    int L  = T / CHUNKS;

    int groups = N >> 2;
    int blocks = (CHUNKS * groups + TPB - 1) / TPB;   // 512 for T=2048,N=8192

    float* adv = out;
    float* ret = out + (size_t)TN;

    gae_fused<<<blocks, TPB>>>(rw, val, dn, adv, ret, N, L, (long long)TN);
}